// round 1
// baseline (speedup 1.0000x reference)
#include <cuda_runtime.h>
#include <math.h>

#define BB   2
#define SS   2048
#define HHID 2048
#define NHQ  16
#define NKVH 4
#define DDIM 128
#define TTOK (BB*SS)   // 4096

// ---------------- scratch (static device globals; no allocation) ----------------
__device__ float g_q [BB*NHQ *SS*DDIM];   // [B][NH][S][D]
__device__ float g_k [BB*NKVH*SS*DDIM];   // [B][NKV][S][D]
__device__ float g_v [BB*NKVH*SS*DDIM];   // [B][NKV][S][D]
__device__ float g_ao[(size_t)TTOK*HHID]; // [B][S][NH*D]

// =====================================================================
// Kernel 1: expert-routed QKV projection (+bias), scatter to head layout
// grid: (32 row-tiles, 24 col-tiles)  col-tiles: 0..15 Q, 16..19 K, 20..23 V
// =====================================================================
__global__ __launch_bounds__(256) void qkv_kernel(
    const float* __restrict__ hs, const int* __restrict__ tt,
    const float* __restrict__ Wq, const float* __restrict__ bq,
    const float* __restrict__ Wk, const float* __restrict__ bk,
    const float* __restrict__ Wv, const float* __restrict__ bv)
{
    const int rt = blockIdx.x, ct = blockIdx.y;
    const int m0 = rt * 128;
    const float* W; const float* bias; int nstr, n0, which, head;
    if (ct < 16)      { W = Wq; bias = bq; nstr = 2048; n0 = ct * 128;       which = 0; head = ct;      }
    else if (ct < 20) { W = Wk; bias = bk; nstr = 512;  n0 = (ct - 16) * 128; which = 1; head = ct - 16; }
    else              { W = Wv; bias = bv; nstr = 512;  n0 = (ct - 20) * 128; which = 2; head = ct - 20; }

    __shared__ float As[16][132];        // transposed A tile: As[k][m]
    __shared__ float Bs[2][16][128];     // both experts' B tiles

    const int tid = threadIdx.x;
    const int tx = tid & 15, ty = tid >> 4;

    int ex[8];
#pragma unroll
    for (int i = 0; i < 8; i++) ex[i] = tt[m0 + ty * 8 + i];

    float acc[8][8];
#pragma unroll
    for (int i = 0; i < 8; i++)
#pragma unroll
        for (int j = 0; j < 8; j++) acc[i][j] = 0.f;

    for (int k0 = 0; k0 < 2048; k0 += 16) {
        // ---- load A tile (128 x 16), transposed store ----
#pragma unroll
        for (int it = 0; it < 2; it++) {
            int f = tid + it * 256;
            int row = f >> 2, kc = f & 3;
            float4 v = *(const float4*)&hs[(size_t)(m0 + row) * 2048 + k0 + kc * 4];
            As[kc * 4 + 0][row] = v.x;
            As[kc * 4 + 1][row] = v.y;
            As[kc * 4 + 2][row] = v.z;
            As[kc * 4 + 3][row] = v.w;
        }
        // ---- load B tiles for both experts (2 x 16 x 128) ----
#pragma unroll
        for (int it = 0; it < 4; it++) {
            int f = tid + it * 256;
            int e = f >> 9, rem = f & 511, kr = rem >> 5, nc = rem & 31;
            float4 v = *(const float4*)&W[(size_t)e * 2048 * nstr + (size_t)(k0 + kr) * nstr + n0 + nc * 4];
            *(float4*)&Bs[e][kr][nc * 4] = v;
        }
        __syncthreads();
#pragma unroll 8
        for (int kk = 0; kk < 16; kk++) {
            float a[8], b0[8], b1[8];
            *(float4*)&a[0]  = *(float4*)&As[kk][ty * 8];
            *(float4*)&a[4]  = *(float4*)&As[kk][ty * 8 + 4];
            *(float4*)&b0[0] = *(float4*)&Bs[0][kk][tx * 8];
            *(float4*)&b0[4] = *(float4*)&Bs[0][kk][tx * 8 + 4];
            *(float4*)&b1[0] = *(float4*)&Bs[1][kk][tx * 8];
            *(float4*)&b1[4] = *(float4*)&Bs[1][kk][tx * 8 + 4];
#pragma unroll
            for (int i = 0; i < 8; i++) {
                const bool e1 = (ex[i] != 0);
#pragma unroll
                for (int j = 0; j < 8; j++) {
                    float b = e1 ? b1[j] : b0[j];
                    acc[i][j] = fmaf(a[i], b, acc[i][j]);
                }
            }
        }
        __syncthreads();
    }

    // ---- epilogue: bias + scatter to [B][h][S][D] ----
#pragma unroll
    for (int i = 0; i < 8; i++) {
        int t = m0 + ty * 8 + i;
        int b = t >> 11, s = t & 2047;
        int e = ex[i];
        float vals[8];
#pragma unroll
        for (int j = 0; j < 8; j++)
            vals[j] = acc[i][j] + bias[e * nstr + n0 + tx * 8 + j];
        float* dst;
        if (which == 0)      dst = &g_q[(size_t)((b * NHQ  + head) * SS + s) * DDIM + tx * 8];
        else if (which == 1) dst = &g_k[(size_t)((b * NKVH + head) * SS + s) * DDIM + tx * 8];
        else                 dst = &g_v[(size_t)((b * NKVH + head) * SS + s) * DDIM + tx * 8];
        *(float4*)&dst[0] = make_float4(vals[0], vals[1], vals[2], vals[3]);
        *(float4*)&dst[4] = make_float4(vals[4], vals[5], vals[6], vals[7]);
    }
}

// =====================================================================
// Kernel 2: RoPE in-place on g_q (isK=0) or g_k (isK=1)
// one thread per (b,h,s,d<64) pair
// =====================================================================
__global__ __launch_bounds__(256) void rope_kernel(
    const float* __restrict__ cosp, const float* __restrict__ sinp, int isK)
{
    float* x = isK ? g_k : g_q;
    const int nh = isK ? NKVH : NHQ;
    int idx = blockIdx.x * 256 + threadIdx.x;
    int d = idx & 63;
    int s = (idx >> 6) & 2047;
    int rest = idx >> 17;          // b*nh + head
    int b = rest / nh;
    size_t base  = ((size_t)rest * SS + s) * DDIM;
    size_t cbase = ((size_t)(b * SS + s)) * DDIM;
    float x0 = x[base + d], x1 = x[base + d + 64];
    float c0 = cosp[cbase + d], c1 = cosp[cbase + d + 64];
    float s0 = sinp[cbase + d], s1 = sinp[cbase + d + 64];
    x[base + d]      = fmaf(x0, c0, -x1 * s0);
    x[base + d + 64] = fmaf(x1, c1,  x0 * s1);
}

// =====================================================================
// Kernel 3: causal flash attention (fp32, online softmax, GQA)
// grid: (16 q-tiles [reversed], B*NH=32). BQ=128, BKV=64.
// dynamic smem: sQt 64KB | sKt 32KB | sV 32KB | sPt 32KB = 160KB
// =====================================================================
__global__ __launch_bounds__(256) void attn_kernel()
{
    extern __shared__ float sm[];
    float* sQt = sm;               // [128 d][128 r]
    float* sKt = sm + 16384;       // [128 d][64 c]
    float* sV  = sm + 24576;       // [64 c][128 d]
    float* sPt = sm + 32768;       // [64 c][128 r]

    const int bh = blockIdx.y;
    const int b = bh >> 4, h = bh & 15, hk = h >> 2;
    const int qt = 15 - blockIdx.x;          // big workloads first
    const int q0 = qt * 128;
    const float* Q = g_q + (size_t)(b * NHQ  + h ) * SS * DDIM;
    const float* K = g_k + (size_t)(b * NKVH + hk) * SS * DDIM;
    const float* V = g_v + (size_t)(b * NKVH + hk) * SS * DDIM;

    const int tid = threadIdx.x;
    const int tx = tid & 15, ty = tid >> 4;

    // ---- load Q tile transposed ----
#pragma unroll
    for (int it = 0; it < 16; it++) {
        int f = tid + it * 256;
        int r = f >> 5, dc = f & 31;
        float4 v = *(const float4*)&Q[(size_t)(q0 + r) * DDIM + dc * 4];
        sQt[(dc * 4 + 0) * 128 + r] = v.x;
        sQt[(dc * 4 + 1) * 128 + r] = v.y;
        sQt[(dc * 4 + 2) * 128 + r] = v.z;
        sQt[(dc * 4 + 3) * 128 + r] = v.w;
    }

    float accO[8][8];
    float mrow[8], lrow[8];
#pragma unroll
    for (int i = 0; i < 8; i++) {
        mrow[i] = -1e30f; lrow[i] = 0.f;
#pragma unroll
        for (int j = 0; j < 8; j++) accO[i][j] = 0.f;
    }

    const float scale = 0.08838834764831845f;   // 1/sqrt(128)
    const int ktiles = 2 * qt + 2;

    for (int kt = 0; kt < ktiles; kt++) {
        const int k0 = kt * 64;
        __syncthreads();   // protect sKt/sV/sPt reuse from previous iteration
        // ---- load K tile transposed ----
#pragma unroll
        for (int it = 0; it < 8; it++) {
            int f = tid + it * 256;
            int c = f >> 5, dc = f & 31;
            float4 v = *(const float4*)&K[(size_t)(k0 + c) * DDIM + dc * 4];
            sKt[(dc * 4 + 0) * 64 + c] = v.x;
            sKt[(dc * 4 + 1) * 64 + c] = v.y;
            sKt[(dc * 4 + 2) * 64 + c] = v.z;
            sKt[(dc * 4 + 3) * 64 + c] = v.w;
        }
        // ---- load V tile natural layout ----
#pragma unroll
        for (int it = 0; it < 8; it++) {
            int f = tid + it * 256;
            int c = f >> 5, dc = f & 31;
            *(float4*)&sV[c * 128 + dc * 4] = *(const float4*)&V[(size_t)(k0 + c) * DDIM + dc * 4];
        }
        __syncthreads();

        // ---- S = Q K^T ----
        float sc[8][4];
#pragma unroll
        for (int i = 0; i < 8; i++)
#pragma unroll
            for (int j = 0; j < 4; j++) sc[i][j] = 0.f;
#pragma unroll 8
        for (int d = 0; d < 128; d++) {
            float qf[8], kf[4];
            *(float4*)&qf[0] = *(float4*)&sQt[d * 128 + ty * 8];
            *(float4*)&qf[4] = *(float4*)&sQt[d * 128 + ty * 8 + 4];
            *(float4*)&kf[0] = *(float4*)&sKt[d * 64 + tx * 4];
#pragma unroll
            for (int i = 0; i < 8; i++)
#pragma unroll
                for (int j = 0; j < 4; j++)
                    sc[i][j] = fmaf(qf[i], kf[j], sc[i][j]);
        }
        // ---- scale + causal mask ----
#pragma unroll
        for (int i = 0; i < 8; i++)
#pragma unroll
            for (int j = 0; j < 4; j++) sc[i][j] *= scale;
        if (k0 + 63 > q0) {
#pragma unroll
            for (int i = 0; i < 8; i++)
#pragma unroll
                for (int j = 0; j < 4; j++)
                    if (k0 + tx * 4 + j > q0 + ty * 8 + i) sc[i][j] = -1e30f;
        }
        // ---- online softmax (row stats replicated across the 16 tx lanes) ----
#pragma unroll
        for (int i = 0; i < 8; i++) {
            float mx = fmaxf(fmaxf(sc[i][0], sc[i][1]), fmaxf(sc[i][2], sc[i][3]));
#pragma unroll
            for (int o = 1; o < 16; o <<= 1) mx = fmaxf(mx, __shfl_xor_sync(0xffffffffu, mx, o));
            float mn = fmaxf(mrow[i], mx);
            float alpha = __expf(mrow[i] - mn);
            mrow[i] = mn;
            float rs = 0.f;
#pragma unroll
            for (int j = 0; j < 4; j++) { float p = __expf(sc[i][j] - mn); sc[i][j] = p; rs += p; }
#pragma unroll
            for (int o = 1; o < 16; o <<= 1) rs += __shfl_xor_sync(0xffffffffu, rs, o);
            lrow[i] = lrow[i] * alpha + rs;
#pragma unroll
            for (int j = 0; j < 8; j++) accO[i][j] *= alpha;
        }
        // ---- stage P transposed ----
#pragma unroll
        for (int i = 0; i < 8; i++)
#pragma unroll
            for (int j = 0; j < 4; j++)
                sPt[(tx * 4 + j) * 128 + ty * 8 + i] = sc[i][j];
        __syncthreads();
        // ---- O += P V ----
#pragma unroll 4
        for (int c = 0; c < 64; c++) {
            float pf[8], vf[8];
            *(float4*)&pf[0] = *(float4*)&sPt[c * 128 + ty * 8];
            *(float4*)&pf[4] = *(float4*)&sPt[c * 128 + ty * 8 + 4];
            *(float4*)&vf[0] = *(float4*)&sV[c * 128 + tx * 8];
            *(float4*)&vf[4] = *(float4*)&sV[c * 128 + tx * 8 + 4];
#pragma unroll
            for (int i = 0; i < 8; i++)
#pragma unroll
                for (int j = 0; j < 8; j++)
                    accO[i][j] = fmaf(pf[i], vf[j], accO[i][j]);
        }
    }

    // ---- epilogue: normalize, write [B][S][NH*D] ----
#pragma unroll
    for (int i = 0; i < 8; i++) {
        float inv = 1.f / lrow[i];
        int srow = q0 + ty * 8 + i;
        float* dst = &g_ao[(size_t)(b * SS + srow) * HHID + h * DDIM + tx * 8];
        *(float4*)&dst[0] = make_float4(accO[i][0] * inv, accO[i][1] * inv, accO[i][2] * inv, accO[i][3] * inv);
        *(float4*)&dst[4] = make_float4(accO[i][4] * inv, accO[i][5] * inv, accO[i][6] * inv, accO[i][7] * inv);
    }
}

// =====================================================================
// Kernel 4: expert-routed output projection. grid: (32, 16)
// =====================================================================
__global__ __launch_bounds__(256) void oproj_kernel(
    const int* __restrict__ tt, const float* __restrict__ Wo, float* __restrict__ out)
{
    const int rt = blockIdx.x, ct = blockIdx.y;
    const int m0 = rt * 128, n0 = ct * 128;

    __shared__ float As[16][132];
    __shared__ float Bs[2][16][128];

    const int tid = threadIdx.x;
    const int tx = tid & 15, ty = tid >> 4;

    int ex[8];
#pragma unroll
    for (int i = 0; i < 8; i++) ex[i] = tt[m0 + ty * 8 + i];

    float acc[8][8];
#pragma unroll
    for (int i = 0; i < 8; i++)
#pragma unroll
        for (int j = 0; j < 8; j++) acc[i][j] = 0.f;

    for (int k0 = 0; k0 < 2048; k0 += 16) {
#pragma unroll
        for (int it = 0; it < 2; it++) {
            int f = tid + it * 256;
            int row = f >> 2, kc = f & 3;
            float4 v = *(const float4*)&g_ao[(size_t)(m0 + row) * 2048 + k0 + kc * 4];
            As[kc * 4 + 0][row] = v.x;
            As[kc * 4 + 1][row] = v.y;
            As[kc * 4 + 2][row] = v.z;
            As[kc * 4 + 3][row] = v.w;
        }
#pragma unroll
        for (int it = 0; it < 4; it++) {
            int f = tid + it * 256;
            int e = f >> 9, rem = f & 511, kr = rem >> 5, nc = rem & 31;
            float4 v = *(const float4*)&Wo[(size_t)e * 2048 * 2048 + (size_t)(k0 + kr) * 2048 + n0 + nc * 4];
            *(float4*)&Bs[e][kr][nc * 4] = v;
        }
        __syncthreads();
#pragma unroll 8
        for (int kk = 0; kk < 16; kk++) {
            float a[8], b0[8], b1[8];
            *(float4*)&a[0]  = *(float4*)&As[kk][ty * 8];
            *(float4*)&a[4]  = *(float4*)&As[kk][ty * 8 + 4];
            *(float4*)&b0[0] = *(float4*)&Bs[0][kk][tx * 8];
            *(float4*)&b0[4] = *(float4*)&Bs[0][kk][tx * 8 + 4];
            *(float4*)&b1[0] = *(float4*)&Bs[1][kk][tx * 8];
            *(float4*)&b1[4] = *(float4*)&Bs[1][kk][tx * 8 + 4];
#pragma unroll
            for (int i = 0; i < 8; i++) {
                const bool e1 = (ex[i] != 0);
#pragma unroll
                for (int j = 0; j < 8; j++) {
                    float b = e1 ? b1[j] : b0[j];
                    acc[i][j] = fmaf(a[i], b, acc[i][j]);
                }
            }
        }
        __syncthreads();
    }

#pragma unroll
    for (int i = 0; i < 8; i++) {
        float* dst = &out[(size_t)(m0 + ty * 8 + i) * 2048 + n0 + tx * 8];
        *(float4*)&dst[0] = make_float4(acc[i][0], acc[i][1], acc[i][2], acc[i][3]);
        *(float4*)&dst[4] = make_float4(acc[i][4], acc[i][5], acc[i][6], acc[i][7]);
    }
}

// =====================================================================
extern "C" void kernel_launch(void* const* d_in, const int* in_sizes, int n_in,
                              void* d_out, int out_size)
{
    const float* hs   = (const float*)d_in[0];
    const int*   tt   = (const int*)  d_in[1];
    const float* cosp = (const float*)d_in[2];
    const float* sinp = (const float*)d_in[3];
    const float* Wq   = (const float*)d_in[4];
    const float* bq   = (const float*)d_in[5];
    const float* Wk   = (const float*)d_in[6];
    const float* bk   = (const float*)d_in[7];
    const float* Wv   = (const float*)d_in[8];
    const float* bv   = (const float*)d_in[9];
    const float* Wo   = (const float*)d_in[10];
    float* out = (float*)d_out;

    cudaFuncSetAttribute(attn_kernel, cudaFuncAttributeMaxDynamicSharedMemorySize, 163840);

    qkv_kernel<<<dim3(32, 24), 256>>>(hs, tt, Wq, bq, Wk, bk, Wv, bv);
    rope_kernel<<<16384, 256>>>(cosp, sinp, 0);   // q: B*NH*S*64 / 256
    rope_kernel<<<4096,  256>>>(cosp, sinp, 1);   // k: B*NKV*S*64 / 256
    attn_kernel<<<dim3(16, 32), 256, 163840>>>();
    oproj_kernel<<<dim3(32, 16), 256>>>(tt, Wo, out);
}

// round 6
// speedup vs baseline: 1.6965x; 1.6965x over previous
#include <cuda_runtime.h>
#include <cstdint>
#include <math.h>

#define BB   2
#define SS   2048
#define HHID 2048
#define NHQ  16
#define NKVH 4
#define DDIM 128
#define TTOK (BB*SS)     // 4096
#define PAD_ROWS 4224    // 33 tiles of 128

// ---------------- scratch ----------------
__device__ __align__(16) int g_src[PAD_ROWS];   // sorted row -> src token (-1 = pad)
__device__ unsigned g_tiles0_dev;
__device__ __align__(16) float g_q [(size_t)BB*NHQ *SS*DDIM];   // [B][NH][S][D]  (post-RoPE)
__device__ __align__(16) float g_k [(size_t)BB*NKVH*SS*DDIM];   // [B][NKV][S][D] (post-RoPE)
__device__ __align__(16) float g_v [(size_t)BB*NKVH*SS*DDIM];
__device__ __align__(16) float g_ao[(size_t)TTOK*HHID];         // [B][S][NH*D] token order

// ===================== kernel: expert scan / permutation =====================
__global__ __launch_bounds__(1024) void scan_kernel(const int* __restrict__ tt)
{
    __shared__ int wtot[32];
    int tid = threadIdx.x, lane = tid & 31, wid = tid >> 5;
    for (int j = tid; j < PAD_ROWS; j += 1024) g_src[j] = -1;
    __syncthreads();

    int t0 = tid * 4;
    int cs[4];
#pragma unroll
    for (int i = 0; i < 4; i++) cs[i] = tt[t0 + i];
    int loc = cs[0] + cs[1] + cs[2] + cs[3];
    int inc = loc;
#pragma unroll
    for (int o = 1; o < 32; o <<= 1) { int v = __shfl_up_sync(0xffffffffu, inc, o); if (lane >= o) inc += v; }
    if (lane == 31) wtot[wid] = inc;
    __syncthreads();
    if (wid == 0) {
        int v = wtot[lane];
#pragma unroll
        for (int o = 1; o < 32; o <<= 1) { int u = __shfl_up_sync(0xffffffffu, v, o); if (lane >= o) v += u; }
        wtot[lane] = v;
    }
    __syncthreads();
    int total1 = wtot[31];
    int base1  = (wid > 0 ? wtot[wid - 1] : 0) + (inc - loc);
    int n0 = TTOK - total1;
    int tiles0 = (n0 + 127) >> 7;
    if (tid == 0) g_tiles0_dev = (unsigned)tiles0;
    int off1 = tiles0 * 128;
    int run1 = base1;
#pragma unroll
    for (int i = 0; i < 4; i++) {
        int idx = t0 + i;
        int dst = cs[i] ? (off1 + run1) : (idx - run1);
        g_src[dst] = idx;
        run1 += cs[i];
    }
}

// ===================== kernel: QKV projection (fp32 SIMT, sorted experts) + bias + RoPE =====================
// grid (33, 24): ct 0..15 Q-heads, 16..19 K-heads, 20..23 V-heads. block 256.
__global__ __launch_bounds__(256) void qkv_kernel(
    const float* __restrict__ hs,
    const float* __restrict__ Wq, const float* __restrict__ bq,
    const float* __restrict__ Wk, const float* __restrict__ bk,
    const float* __restrict__ Wv, const float* __restrict__ bv,
    const float* __restrict__ cosp, const float* __restrict__ sinp)
{
    const int rt = blockIdx.x, ct = blockIdx.y;
    const int tiles0 = (int)g_tiles0_dev;
    const int e = (rt < tiles0) ? 0 : 1;
    const int m0 = rt * 128;

    const float* W; const float* bias; int nstr, n0, which, head;
    if (ct < 16)      { W = Wq; bias = bq; nstr = 2048; n0 = ct * 128;        which = 0; head = ct;      }
    else if (ct < 20) { W = Wk; bias = bk; nstr = 512;  n0 = (ct - 16) * 128; which = 1; head = ct - 16; }
    else              { W = Wv; bias = bv; nstr = 512;  n0 = (ct - 20) * 128; which = 2; head = ct - 20; }
    W    += (size_t)e * 2048 * nstr;      // single expert for this tile
    bias += (size_t)e * nstr;

    __shared__ float As[16][132];         // transposed A tile: As[k][m]
    __shared__ float Bs[16][128];

    const int tid = threadIdx.x;
    const int tx = tid & 15, ty = tid >> 4;

    // A loader ownership: rows arow0 and arow0+64, k-granule kc
    const int arow0 = tid >> 2, kc = tid & 3;
    const int asrc0 = g_src[m0 + arow0];
    const int asrc1 = g_src[m0 + arow0 + 64];

    float acc[8][8];
#pragma unroll
    for (int i = 0; i < 8; i++)
#pragma unroll
        for (int j = 0; j < 8; j++) acc[i][j] = 0.f;

    for (int k0 = 0; k0 < 2048; k0 += 16) {
        // ---- A tile (gathered rows, transposed store) ----
        {
            float4 v0 = make_float4(0.f, 0.f, 0.f, 0.f);
            float4 v1 = make_float4(0.f, 0.f, 0.f, 0.f);
            if (asrc0 >= 0) v0 = *(const float4*)&hs[(size_t)asrc0 * 2048 + k0 + kc * 4];
            if (asrc1 >= 0) v1 = *(const float4*)&hs[(size_t)asrc1 * 2048 + k0 + kc * 4];
            As[kc * 4 + 0][arow0] = v0.x; As[kc * 4 + 1][arow0] = v0.y;
            As[kc * 4 + 2][arow0] = v0.z; As[kc * 4 + 3][arow0] = v0.w;
            As[kc * 4 + 0][arow0 + 64] = v1.x; As[kc * 4 + 1][arow0 + 64] = v1.y;
            As[kc * 4 + 2][arow0 + 64] = v1.z; As[kc * 4 + 3][arow0 + 64] = v1.w;
        }
        // ---- B tile (single expert, 16 x 128) ----
#pragma unroll
        for (int it = 0; it < 2; it++) {
            int f = tid + it * 256;
            int kr = f >> 5, nc = f & 31;
            *(float4*)&Bs[kr][nc * 4] = *(const float4*)&W[(size_t)(k0 + kr) * nstr + n0 + nc * 4];
        }
        __syncthreads();
#pragma unroll 8
        for (int kk = 0; kk < 16; kk++) {
            float a[8], b[8];
            *(float4*)&a[0] = *(float4*)&As[kk][ty * 8];
            *(float4*)&a[4] = *(float4*)&As[kk][ty * 8 + 4];
            *(float4*)&b[0] = *(float4*)&Bs[kk][tx * 8];
            *(float4*)&b[4] = *(float4*)&Bs[kk][tx * 8 + 4];
#pragma unroll
            for (int i = 0; i < 8; i++)
#pragma unroll
                for (int j = 0; j < 8; j++)
                    acc[i][j] = fmaf(a[i], b[j], acc[i][j]);
        }
        __syncthreads();
    }

    // ---- epilogue: bias + fused RoPE (shfl pair) + scatter ----
    const float* bp = bias + n0;
#pragma unroll
    for (int i = 0; i < 8; i++) {
        const int row = m0 + ty * 8 + i;
        const int src = g_src[row];
        const int sEff = (src >= 0) ? src : 0;
        const int b = sEff >> 11, s = sEff & 2047;

        float v8[8];
#pragma unroll
        for (int j = 0; j < 8; j++) v8[j] = acc[i][j] + __ldg(&bp[tx * 8 + j]);

        if (which < 2) {
            // partner (tx^8, same ty) is lane^8 in the same warp
            float p8[8];
#pragma unroll
            for (int j = 0; j < 8; j++) p8[j] = __shfl_xor_sync(0xffffffffu, v8[j], 8);
            const size_t cb = ((size_t)(b * 2048 + s)) * 128;
#pragma unroll
            for (int j = 0; j < 8; j++) {
                int col = tx * 8 + j;
                float c  = __ldg(&cosp[cb + col]);
                float sn = __ldg(&sinp[cb + col]);
                v8[j] = (tx < 8) ? (v8[j] * c - p8[j] * sn)
                                 : (v8[j] * c + p8[j] * sn);
            }
        }

        if (src >= 0) {
            float* dst;
            if (which == 0)      dst = &g_q[((size_t)((b * NHQ  + head) * SS + s)) * DDIM + tx * 8];
            else if (which == 1) dst = &g_k[((size_t)((b * NKVH + head) * SS + s)) * DDIM + tx * 8];
            else                 dst = &g_v[((size_t)((b * NKVH + head) * SS + s)) * DDIM + tx * 8];
            *(float4*)&dst[0] = make_float4(v8[0], v8[1], v8[2], v8[3]);
            *(float4*)&dst[4] = make_float4(v8[4], v8[5], v8[6], v8[7]);
        }
    }
}

// ===================== kernel: causal flash attention (fp32 SIMT) — unchanged from Round 1 =====================
__global__ __launch_bounds__(256) void attn_kernel()
{
    extern __shared__ float sm[];
    float* sQt = sm;               // [128 d][128 r]
    float* sKt = sm + 16384;       // [128 d][64 c]
    float* sV  = sm + 24576;       // [64 c][128 d]
    float* sPt = sm + 32768;       // [64 c][128 r]

    const int bh = blockIdx.y;
    const int b = bh >> 4, h = bh & 15, hk = h >> 2;
    const int qt = 15 - blockIdx.x;
    const int q0 = qt * 128;
    const float* Q = g_q + (size_t)(b * NHQ  + h ) * SS * DDIM;
    const float* K = g_k + (size_t)(b * NKVH + hk) * SS * DDIM;
    const float* V = g_v + (size_t)(b * NKVH + hk) * SS * DDIM;

    const int tid = threadIdx.x;
    const int tx = tid & 15, ty = tid >> 4;

#pragma unroll
    for (int it = 0; it < 16; it++) {
        int f = tid + it * 256;
        int r = f >> 5, dc = f & 31;
        float4 v = *(const float4*)&Q[(size_t)(q0 + r) * DDIM + dc * 4];
        sQt[(dc * 4 + 0) * 128 + r] = v.x;
        sQt[(dc * 4 + 1) * 128 + r] = v.y;
        sQt[(dc * 4 + 2) * 128 + r] = v.z;
        sQt[(dc * 4 + 3) * 128 + r] = v.w;
    }

    float accO[8][8];
    float mrow[8], lrow[8];
#pragma unroll
    for (int i = 0; i < 8; i++) {
        mrow[i] = -1e30f; lrow[i] = 0.f;
#pragma unroll
        for (int j = 0; j < 8; j++) accO[i][j] = 0.f;
    }

    const float scale = 0.08838834764831845f;
    const int ktiles = 2 * qt + 2;

    for (int kt = 0; kt < ktiles; kt++) {
        const int k0 = kt * 64;
        __syncthreads();
#pragma unroll
        for (int it = 0; it < 8; it++) {
            int f = tid + it * 256;
            int c = f >> 5, dc = f & 31;
            float4 v = *(const float4*)&K[(size_t)(k0 + c) * DDIM + dc * 4];
            sKt[(dc * 4 + 0) * 64 + c] = v.x;
            sKt[(dc * 4 + 1) * 64 + c] = v.y;
            sKt[(dc * 4 + 2) * 64 + c] = v.z;
            sKt[(dc * 4 + 3) * 64 + c] = v.w;
        }
#pragma unroll
        for (int it = 0; it < 8; it++) {
            int f = tid + it * 256;
            int c = f >> 5, dc = f & 31;
            *(float4*)&sV[c * 128 + dc * 4] = *(const float4*)&V[(size_t)(k0 + c) * DDIM + dc * 4];
        }
        __syncthreads();

        float sc[8][4];
#pragma unroll
        for (int i = 0; i < 8; i++)
#pragma unroll
            for (int j = 0; j < 4; j++) sc[i][j] = 0.f;
#pragma unroll 8
        for (int d = 0; d < 128; d++) {
            float qf[8], kf[4];
            *(float4*)&qf[0] = *(float4*)&sQt[d * 128 + ty * 8];
            *(float4*)&qf[4] = *(float4*)&sQt[d * 128 + ty * 8 + 4];
            *(float4*)&kf[0] = *(float4*)&sKt[d * 64 + tx * 4];
#pragma unroll
            for (int i = 0; i < 8; i++)
#pragma unroll
                for (int j = 0; j < 4; j++)
                    sc[i][j] = fmaf(qf[i], kf[j], sc[i][j]);
        }
#pragma unroll
        for (int i = 0; i < 8; i++)
#pragma unroll
            for (int j = 0; j < 4; j++) sc[i][j] *= scale;
        if (k0 + 63 > q0) {
#pragma unroll
            for (int i = 0; i < 8; i++)
#pragma unroll
                for (int j = 0; j < 4; j++)
                    if (k0 + tx * 4 + j > q0 + ty * 8 + i) sc[i][j] = -1e30f;
        }
#pragma unroll
        for (int i = 0; i < 8; i++) {
            float mx = fmaxf(fmaxf(sc[i][0], sc[i][1]), fmaxf(sc[i][2], sc[i][3]));
#pragma unroll
            for (int o = 1; o < 16; o <<= 1) mx = fmaxf(mx, __shfl_xor_sync(0xffffffffu, mx, o));
            float mn = fmaxf(mrow[i], mx);
            float alpha = __expf(mrow[i] - mn);
            mrow[i] = mn;
            float rs = 0.f;
#pragma unroll
            for (int j = 0; j < 4; j++) { float p = __expf(sc[i][j] - mn); sc[i][j] = p; rs += p; }
#pragma unroll
            for (int o = 1; o < 16; o <<= 1) rs += __shfl_xor_sync(0xffffffffu, rs, o);
            lrow[i] = lrow[i] * alpha + rs;
#pragma unroll
            for (int j = 0; j < 8; j++) accO[i][j] *= alpha;
        }
#pragma unroll
        for (int i = 0; i < 8; i++)
#pragma unroll
            for (int j = 0; j < 4; j++)
                sPt[(tx * 4 + j) * 128 + ty * 8 + i] = sc[i][j];
        __syncthreads();
#pragma unroll 4
        for (int c = 0; c < 64; c++) {
            float pf[8], vf[8];
            *(float4*)&pf[0] = *(float4*)&sPt[c * 128 + ty * 8];
            *(float4*)&pf[4] = *(float4*)&sPt[c * 128 + ty * 8 + 4];
            *(float4*)&vf[0] = *(float4*)&sV[c * 128 + tx * 8];
            *(float4*)&vf[4] = *(float4*)&sV[c * 128 + tx * 8 + 4];
#pragma unroll
            for (int i = 0; i < 8; i++)
#pragma unroll
                for (int j = 0; j < 8; j++)
                    accO[i][j] = fmaf(pf[i], vf[j], accO[i][j]);
        }
    }

    // ---- epilogue: normalize, write token-order [B][S][NH*D] ----
#pragma unroll
    for (int i = 0; i < 8; i++) {
        float inv = 1.f / lrow[i];
        int srow = q0 + ty * 8 + i;
        float* dst = &g_ao[(size_t)(b * SS + srow) * HHID + h * DDIM + tx * 8];
        *(float4*)&dst[0] = make_float4(accO[i][0] * inv, accO[i][1] * inv, accO[i][2] * inv, accO[i][3] * inv);
        *(float4*)&dst[4] = make_float4(accO[i][4] * inv, accO[i][5] * inv, accO[i][6] * inv, accO[i][7] * inv);
    }
}

// ===================== kernel: O projection (fp32 SIMT, sorted experts) =====================
// grid (33, 16). block 256.
__global__ __launch_bounds__(256) void oproj_kernel(
    const float* __restrict__ Wo, float* __restrict__ out)
{
    const int rt = blockIdx.x, ct = blockIdx.y;
    const int tiles0 = (int)g_tiles0_dev;
    const int e = (rt < tiles0) ? 0 : 1;
    const int m0 = rt * 128, n0 = ct * 128;
    const float* W = Wo + (size_t)e * 2048 * 2048;

    __shared__ float As[16][132];
    __shared__ float Bs[16][128];

    const int tid = threadIdx.x;
    const int tx = tid & 15, ty = tid >> 4;

    const int arow0 = tid >> 2, kc = tid & 3;
    const int asrc0 = g_src[m0 + arow0];
    const int asrc1 = g_src[m0 + arow0 + 64];

    float acc[8][8];
#pragma unroll
    for (int i = 0; i < 8; i++)
#pragma unroll
        for (int j = 0; j < 8; j++) acc[i][j] = 0.f;

    for (int k0 = 0; k0 < 2048; k0 += 16) {
        {
            float4 v0 = make_float4(0.f, 0.f, 0.f, 0.f);
            float4 v1 = make_float4(0.f, 0.f, 0.f, 0.f);
            if (asrc0 >= 0) v0 = *(const float4*)&g_ao[(size_t)asrc0 * 2048 + k0 + kc * 4];
            if (asrc1 >= 0) v1 = *(const float4*)&g_ao[(size_t)asrc1 * 2048 + k0 + kc * 4];
            As[kc * 4 + 0][arow0] = v0.x; As[kc * 4 + 1][arow0] = v0.y;
            As[kc * 4 + 2][arow0] = v0.z; As[kc * 4 + 3][arow0] = v0.w;
            As[kc * 4 + 0][arow0 + 64] = v1.x; As[kc * 4 + 1][arow0 + 64] = v1.y;
            As[kc * 4 + 2][arow0 + 64] = v1.z; As[kc * 4 + 3][arow0 + 64] = v1.w;
        }
#pragma unroll
        for (int it = 0; it < 2; it++) {
            int f = tid + it * 256;
            int kr = f >> 5, nc = f & 31;
            *(float4*)&Bs[kr][nc * 4] = *(const float4*)&W[(size_t)(k0 + kr) * 2048 + n0 + nc * 4];
        }
        __syncthreads();
#pragma unroll 8
        for (int kk = 0; kk < 16; kk++) {
            float a[8], b[8];
            *(float4*)&a[0] = *(float4*)&As[kk][ty * 8];
            *(float4*)&a[4] = *(float4*)&As[kk][ty * 8 + 4];
            *(float4*)&b[0] = *(float4*)&Bs[kk][tx * 8];
            *(float4*)&b[4] = *(float4*)&Bs[kk][tx * 8 + 4];
#pragma unroll
            for (int i = 0; i < 8; i++)
#pragma unroll
                for (int j = 0; j < 8; j++)
                    acc[i][j] = fmaf(a[i], b[j], acc[i][j]);
        }
        __syncthreads();
    }

#pragma unroll
    for (int i = 0; i < 8; i++) {
        const int src = g_src[m0 + ty * 8 + i];
        if (src >= 0) {
            float* dst = &out[(size_t)src * 2048 + n0 + tx * 8];
            *(float4*)&dst[0] = make_float4(acc[i][0], acc[i][1], acc[i][2], acc[i][3]);
            *(float4*)&dst[4] = make_float4(acc[i][4], acc[i][5], acc[i][6], acc[i][7]);
        }
    }
}

// =====================================================================
extern "C" void kernel_launch(void* const* d_in, const int* in_sizes, int n_in,
                              void* d_out, int out_size)
{
    const float* hs   = (const float*)d_in[0];
    const int*   tt   = (const int*)  d_in[1];
    const float* cosp = (const float*)d_in[2];
    const float* sinp = (const float*)d_in[3];
    const float* Wq   = (const float*)d_in[4];
    const float* bq   = (const float*)d_in[5];
    const float* Wk   = (const float*)d_in[6];
    const float* bk   = (const float*)d_in[7];
    const float* Wv   = (const float*)d_in[8];
    const float* bv   = (const float*)d_in[9];
    const float* Wo   = (const float*)d_in[10];
    float* out = (float*)d_out;

    cudaFuncSetAttribute(attn_kernel, cudaFuncAttributeMaxDynamicSharedMemorySize, 163840);

    scan_kernel<<<1, 1024>>>(tt);
    qkv_kernel<<<dim3(33, 24), 256>>>(hs, Wq, bq, Wk, bk, Wv, bv, cosp, sinp);
    attn_kernel<<<dim3(16, 32), 256, 163840>>>();
    oproj_kernel<<<dim3(33, 16), 256>>>(Wo, out);
}